// round 15
// baseline (speedup 1.0000x reference)
#include <cuda_runtime.h>
#include <cuda_fp16.h>
#include <cuda_bf16.h>
#include <cstdint>

#define N_NODES 50000
#define HD 128
#define E_MAX 600000

// ---------------- scratch (device globals; no dynamic allocation) ----------
__device__ float  g_dis[N_NODES];                 // rsqrt(degree incl. self-loop)
__device__ int    g_cnt[N_NODES];                 // in-degree histogram
__device__ int2   g_seg[N_NODES];                 // (beg, deg) of node's segment
__device__ int    g_cursor[N_NODES];              // fill cursors
__device__ int    g_total;                        // ticket counter (reset by fill)
__device__ int2   g_csr[E_MAX];                   // packed (src, norm), segment-grouped
__device__ __half g_xwh[(size_t)N_NODES * HD];    // layer-1 x @ W^T (fp16)
__device__ __half g_xwh2[(size_t)N_NODES * HD];   // layer-2 h1 @ W^T (fp16)
__device__ int    g_is64;                         // 1 if edge_index stored as int64

struct __align__(8) h4 { __half2 a, b; };

// ---------------- init + dtype detect (merged) ------------------------------
__global__ void initdetect_kernel(const int* __restrict__ ew, int n) {
    int i = blockIdx.x * blockDim.x + threadIdx.x;
    if (i < n) g_cnt[i] = 0;
    if (blockIdx.x == 0) {
        __shared__ int found;
        if (threadIdx.x == 0) found = 0;
        __syncthreads();
        int f = 0;
        for (int j = threadIdx.x; j < 2048; j += blockDim.x)
            if (ew[2 * j + 1] != 0) f = 1;
        if (f) atomicOr(&found, 1);
        __syncthreads();
        if (threadIdx.x == 0) g_is64 = found ? 0 : 1;
    }
}

__global__ void hist_kernel(const int* __restrict__ ew, int E) {
    int e = blockIdx.x * blockDim.x + threadIdx.x;
    if (e >= E) return;
    int d = g_is64 ? ew[2 * (E + e)] : ew[E + e];
    atomicAdd(&g_cnt[d], 1);
}

// ---- single-launch segment assignment (ticket scan) ------------------------
__global__ void scanM_kernel(int n) {
    __shared__ int sm[256];
    __shared__ int base_sh;
    int i = blockIdx.x * 256 + threadIdx.x;
    int v = (i < n) ? g_cnt[i] : 0;
    if (i < n) g_dis[i] = rsqrtf((float)(v + 1));
    sm[threadIdx.x] = v;
    __syncthreads();
    #pragma unroll
    for (int off = 1; off < 256; off <<= 1) {
        int t = (threadIdx.x >= off) ? sm[threadIdx.x - off] : 0;
        __syncthreads();
        sm[threadIdx.x] += t;
        __syncthreads();
    }
    if (threadIdx.x == 255) base_sh = atomicAdd(&g_total, sm[255]);
    __syncthreads();
    if (i < n) {
        int beg = base_sh + sm[threadIdx.x] - v;
        g_seg[i] = make_int2(beg, v);
        g_cursor[i] = beg;
    }
}

__global__ void fill_kernel(const int* __restrict__ ew, int E) {
    if (blockIdx.x == 0 && threadIdx.x == 0) g_total = 0;   // reset for replays
    int e = blockIdx.x * blockDim.x + threadIdx.x;
    if (e >= E) return;
    int s, d;
    if (g_is64) { s = ew[2 * e]; d = ew[2 * (E + e)]; }
    else        { s = ew[e];     d = ew[E + e]; }
    int pos = atomicAdd(&g_cursor[d], 1);
    float nm = g_dis[s] * g_dis[d];
    g_csr[pos] = make_int2(s, __float_as_int(nm));
}

// ---------------- shared GEMM helpers ---------------------------------------
static __device__ __forceinline__ uint32_t smem_u32(const void* p) {
    uint32_t a;
    asm("{ .reg .u64 t; cvta.to.shared.u64 t, %1; cvt.u32.u64 %0, t; }"
        : "=r"(a) : "l"(p));
    return a;
}
// 128B-row tile (B tiles and layer-1 A tiles): chunk c in 0..7
static __device__ __forceinline__ uint32_t sw_off(int r, int c) {
    return (uint32_t)(r * 128 + (((c) << 4) ^ ((r & 7) << 4)));
}
// 256B-row tile (fused-kernel A tiles): chunk c in 0..15 (XOR hits bits 4-6 only)
static __device__ __forceinline__ uint32_t sw_off_a(int r, int c) {
    return (uint32_t)(r * 256 + (((c) << 4) ^ ((r & 7) << 4)));
}
static __device__ __forceinline__ void split_pair(float x, float y,
                                                  uint32_t& hi, uint32_t& lo) {
    __nv_bfloat162 h = __floats2bfloat162_rn(x, y);
    __nv_bfloat162 l = __floats2bfloat162_rn(x - __bfloat162float(h.x),
                                             y - __bfloat162float(h.y));
    hi = *reinterpret_cast<uint32_t*>(&h);
    lo = *reinterpret_cast<uint32_t*>(&l);
}

#define LDSM_X4(r, addr) \
    asm volatile("ldmatrix.sync.aligned.m8n8.x4.shared.b16 {%0,%1,%2,%3}, [%4];" \
                 : "=r"((r)[0]), "=r"((r)[1]), "=r"((r)[2]), "=r"((r)[3]) : "r"(addr))
#define LDSM_X2(r, addr) \
    asm volatile("ldmatrix.sync.aligned.m8n8.x2.shared.b16 {%0,%1}, [%2];" \
                 : "=r"((r)[0]), "=r"((r)[1]) : "r"(addr))
#define MMA_BF16(d, a, b) \
    asm volatile("mma.sync.aligned.m16n8k16.row.col.f32.bf16.bf16.f32 " \
                 "{%0,%1,%2,%3}, {%4,%5,%6,%7}, {%8,%9}, {%0,%1,%2,%3};" \
                 : "+f"((d)[0]), "+f"((d)[1]), "+f"((d)[2]), "+f"((d)[3]) \
                 : "r"((a)[0]), "r"((a)[1]), "r"((a)[2]), "r"((a)[3]), \
                   "r"((b)[0]), "r"((b)[1]))

// per-node aggregation into a float4 (lane covers cols 4l..4l+3)
static __device__ __forceinline__ float4
agg_node(int node, int lane, const float* __restrict__ bias,
         const __half* __restrict__ xwh)
{
    int2 seg = g_seg[node];
    int beg = seg.x, end = seg.x + seg.y;
    float ds = g_dis[node];
    float sc = ds * ds;
    h4 hs = ((const h4*)(xwh + (size_t)node * HD))[lane];
    float2 s0 = __half22float2(hs.a), s1 = __half22float2(hs.b);
    float4 b4 = ((const float4*)bias)[lane];
    float4 acc;
    acc.x = fmaf(sc, s0.x, b4.x);
    acc.y = fmaf(sc, s0.y, b4.y);
    acc.z = fmaf(sc, s1.x, b4.z);
    acc.w = fmaf(sc, s1.y, b4.w);
    int p = beg;
    for (; p + 4 <= end; p += 4) {
        int2 e0 = g_csr[p + 0];
        int2 e1 = g_csr[p + 1];
        int2 e2 = g_csr[p + 2];
        int2 e3 = g_csr[p + 3];
        h4 h0 = ((const h4*)(xwh + (size_t)e0.x * HD))[lane];
        h4 h1 = ((const h4*)(xwh + (size_t)e1.x * HD))[lane];
        h4 h2 = ((const h4*)(xwh + (size_t)e2.x * HD))[lane];
        h4 h3 = ((const h4*)(xwh + (size_t)e3.x * HD))[lane];
        float n0 = __int_as_float(e0.y), n1 = __int_as_float(e1.y);
        float n2 = __int_as_float(e2.y), n3 = __int_as_float(e3.y);
        float2 a0 = __half22float2(h0.a), c0 = __half22float2(h0.b);
        float2 a1 = __half22float2(h1.a), c1 = __half22float2(h1.b);
        float2 a2 = __half22float2(h2.a), c2 = __half22float2(h2.b);
        float2 a3 = __half22float2(h3.a), c3 = __half22float2(h3.b);
        acc.x = fmaf(n0, a0.x, acc.x); acc.y = fmaf(n0, a0.y, acc.y);
        acc.z = fmaf(n0, c0.x, acc.z); acc.w = fmaf(n0, c0.y, acc.w);
        acc.x = fmaf(n1, a1.x, acc.x); acc.y = fmaf(n1, a1.y, acc.y);
        acc.z = fmaf(n1, c1.x, acc.z); acc.w = fmaf(n1, c1.y, acc.w);
        acc.x = fmaf(n2, a2.x, acc.x); acc.y = fmaf(n2, a2.y, acc.y);
        acc.z = fmaf(n2, c2.x, acc.z); acc.w = fmaf(n2, c2.y, acc.w);
        acc.x = fmaf(n3, a3.x, acc.x); acc.y = fmaf(n3, a3.y, acc.y);
        acc.z = fmaf(n3, c3.x, acc.z); acc.w = fmaf(n3, c3.y, acc.w);
    }
    for (; p < end; p++) {
        int2 e = g_csr[p];
        h4 hv = ((const h4*)(xwh + (size_t)e.x * HD))[lane];
        float nm = __int_as_float(e.y);
        float2 fa = __half22float2(hv.a), fb = __half22float2(hv.b);
        acc.x = fmaf(nm, fa.x, acc.x); acc.y = fmaf(nm, fa.y, acc.y);
        acc.z = fmaf(nm, fb.x, acc.z); acc.w = fmaf(nm, fb.y, acc.w);
    }
    return acc;
}

// =========== layer-1 GEMM: XWH = fp16(X @ W^T), bf16 split ================
#define GEMM_SMEM_BYTES 65536
#define AHI_OFF 0
#define ALO_OFF 16384
#define BHI_OFF 32768
#define BLO_OFF 49152

__global__ void __launch_bounds__(256, 2)
gcn_gemm(const float* __restrict__ X, const float* __restrict__ W,
         __half* __restrict__ XWH, int nrows)
{
    extern __shared__ char smem[];
    const uint32_t smb = smem_u32(smem);
    const int tid = threadIdx.x;
    const int lane = tid & 31;
    const int wid = tid >> 5;
    const int warp_m = wid & 3;
    const int warp_n = wid >> 2;
    const int row0 = blockIdx.x * 128;

    float acc[2][8][4];
    #pragma unroll
    for (int mi = 0; mi < 2; mi++)
        #pragma unroll
        for (int nj = 0; nj < 8; nj++)
            #pragma unroll
            for (int q = 0; q < 4; q++) acc[mi][nj][q] = 0.f;

    const int arow = lane & 15;
    const int akh  = lane >> 4;
    const int brow = lane & 7;
    const int bkh  = (lane >> 3) & 1;

    #pragma unroll
    for (int t = 0; t < 2; t++) {
        const int k0 = t * 64;
        #pragma unroll
        for (int it = 0; it < 4; it++) {
            int id = tid + 256 * it;
            int r = id >> 3, c8 = id & 7;
            uint32_t so = sw_off(r, c8);
            int gr = row0 + r;
            float4 xa = make_float4(0.f, 0.f, 0.f, 0.f), xb = xa;
            if (gr < nrows) {
                const float4* xp = (const float4*)(X + (size_t)gr * HD + k0 + c8 * 8);
                xa = xp[0]; xb = xp[1];
            }
            uint4 hi4, lo4;
            split_pair(xa.x, xa.y, hi4.x, lo4.x);
            split_pair(xa.z, xa.w, hi4.y, lo4.y);
            split_pair(xb.x, xb.y, hi4.z, lo4.z);
            split_pair(xb.z, xb.w, hi4.w, lo4.w);
            *(uint4*)(smem + AHI_OFF + so) = hi4;
            *(uint4*)(smem + ALO_OFF + so) = lo4;
            const float4* wp = (const float4*)(W + (size_t)r * HD + k0 + c8 * 8);
            float4 wa = wp[0], wb = wp[1];
            split_pair(wa.x, wa.y, hi4.x, lo4.x);
            split_pair(wa.z, wa.w, hi4.y, lo4.y);
            split_pair(wb.x, wb.y, hi4.z, lo4.z);
            split_pair(wb.z, wb.w, hi4.w, lo4.w);
            *(uint4*)(smem + BHI_OFF + so) = hi4;
            *(uint4*)(smem + BLO_OFF + so) = lo4;
        }
        __syncthreads();

        #pragma unroll
        for (int kc = 0; kc < 4; kc++) {
            uint32_t ahi[2][4], alo[2][4];
            #pragma unroll
            for (int mi = 0; mi < 2; mi++) {
                int rr = warp_m * 32 + mi * 16 + arow;
                uint32_t off = sw_off(rr, 2 * kc + akh);
                LDSM_X4(ahi[mi], smb + AHI_OFF + off);
                LDSM_X4(alo[mi], smb + ALO_OFF + off);
            }
            #pragma unroll
            for (int nj = 0; nj < 8; nj++) {
                int nr = warp_n * 64 + nj * 8 + brow;
                uint32_t boff = sw_off(nr, 2 * kc + bkh);
                uint32_t bh[2], bl[2];
                LDSM_X2(bh, smb + BHI_OFF + boff);
                LDSM_X2(bl, smb + BLO_OFF + boff);
                #pragma unroll
                for (int mi = 0; mi < 2; mi++) {
                    MMA_BF16(acc[mi][nj], ahi[mi], bh);
                    MMA_BF16(acc[mi][nj], ahi[mi], bl);
                    MMA_BF16(acc[mi][nj], alo[mi], bh);
                }
            }
        }
        __syncthreads();
    }

    const int gr0 = lane >> 2;
    const int gc0 = (lane & 3) * 2;
    #pragma unroll
    for (int mi = 0; mi < 2; mi++) {
        #pragma unroll
        for (int nj = 0; nj < 8; nj++) {
            int cc = warp_n * 64 + nj * 8 + gc0;
            int r1 = row0 + warp_m * 32 + mi * 16 + gr0;
            if (r1 < nrows) {
                __half2 h = __floats2half2_rn(acc[mi][nj][0], acc[mi][nj][1]);
                *(__half2*)&XWH[(size_t)r1 * HD + cc] = h;
            }
            int r2 = r1 + 8;
            if (r2 < nrows) {
                __half2 h = __floats2half2_rn(acc[mi][nj][2], acc[mi][nj][3]);
                *(__half2*)&XWH[(size_t)r2 * HD + cc] = h;
            }
        }
    }
}

// =========== fused layer: XWH2 = fp16( agg1(XWH) @ W2^T ) =================
// Phase 1: each warp aggregates 16 rows (h1 in registers), splits to bf16
// hi/lo directly into persistent A smem tiles [128][128] bf16 (256B rows).
// Phase 2: standard MMA with W2 B-tiles per 64-wide k-tile.
#define FUSED_SMEM_BYTES 98304
#define FA_HI 0
#define FA_LO 32768
#define FB_HI 65536
#define FB_LO 81920

__global__ void __launch_bounds__(256, 2)
gcn_agg_gemm(const float* __restrict__ bias1, const float* __restrict__ W2,
             const __half* __restrict__ XWH_src, __half* __restrict__ XWH_dst,
             int nrows)
{
    extern __shared__ char smem[];
    const uint32_t smb = smem_u32(smem);
    const int tid = threadIdx.x;
    const int lane = tid & 31;
    const int wid = tid >> 5;
    const int warp_m = wid & 3;
    const int warp_n = wid >> 2;
    const int row0 = blockIdx.x * 128;

    // ---- phase 1: aggregate 16 rows per warp -> A smem (bf16 hi/lo) ----
    {
        uint32_t wb = (uint32_t)((lane >> 1) << 4) + (uint32_t)(lane & 1) * 8;
        #pragma unroll 2
        for (int i = 0; i < 16; i++) {
            int r = wid * 16 + i;
            int node = row0 + r;
            float4 a = make_float4(0.f, 0.f, 0.f, 0.f);
            if (node < nrows) a = agg_node(node, lane, bias1, XWH_src);
            uint32_t hi0, lo0, hi1, lo1;
            split_pair(a.x, a.y, hi0, lo0);
            split_pair(a.z, a.w, hi1, lo1);
            uint32_t off = (uint32_t)(r * 256) + (wb ^ ((uint32_t)(r & 7) << 4));
            *(uint2*)(smem + FA_HI + off) = make_uint2(hi0, hi1);
            *(uint2*)(smem + FA_LO + off) = make_uint2(lo0, lo1);
        }
    }
    __syncthreads();

    float acc[2][8][4];
    #pragma unroll
    for (int mi = 0; mi < 2; mi++)
        #pragma unroll
        for (int nj = 0; nj < 8; nj++)
            #pragma unroll
            for (int q = 0; q < 4; q++) acc[mi][nj][q] = 0.f;

    const int arow = lane & 15;
    const int akh  = lane >> 4;
    const int brow = lane & 7;
    const int bkh  = (lane >> 3) & 1;

    #pragma unroll
    for (int t = 0; t < 2; t++) {
        const int k0 = t * 64;
        if (t > 0) __syncthreads();
        // load W2 B-tile
        #pragma unroll
        for (int it = 0; it < 4; it++) {
            int id = tid + 256 * it;
            int r = id >> 3, c8 = id & 7;
            uint32_t so = sw_off(r, c8);
            const float4* wp = (const float4*)(W2 + (size_t)r * HD + k0 + c8 * 8);
            float4 wa = wp[0], wb2 = wp[1];
            uint4 hi4, lo4;
            split_pair(wa.x, wa.y, hi4.x, lo4.x);
            split_pair(wa.z, wa.w, hi4.y, lo4.y);
            split_pair(wb2.x, wb2.y, hi4.z, lo4.z);
            split_pair(wb2.z, wb2.w, hi4.w, lo4.w);
            *(uint4*)(smem + FB_HI + so) = hi4;
            *(uint4*)(smem + FB_LO + so) = lo4;
        }
        __syncthreads();

        #pragma unroll
        for (int kc = 0; kc < 4; kc++) {
            uint32_t ahi[2][4], alo[2][4];
            #pragma unroll
            for (int mi = 0; mi < 2; mi++) {
                int rr = warp_m * 32 + mi * 16 + arow;
                int c = t * 8 + 2 * kc + akh;
                uint32_t off = sw_off_a(rr, c);
                LDSM_X4(ahi[mi], smb + FA_HI + off);
                LDSM_X4(alo[mi], smb + FA_LO + off);
            }
            #pragma unroll
            for (int nj = 0; nj < 8; nj++) {
                int nr = warp_n * 64 + nj * 8 + brow;
                uint32_t boff = sw_off(nr, 2 * kc + bkh);
                uint32_t bh[2], bl[2];
                LDSM_X2(bh, smb + FB_HI + boff);
                LDSM_X2(bl, smb + FB_LO + boff);
                #pragma unroll
                for (int mi = 0; mi < 2; mi++) {
                    MMA_BF16(acc[mi][nj], ahi[mi], bh);
                    MMA_BF16(acc[mi][nj], ahi[mi], bl);
                    MMA_BF16(acc[mi][nj], alo[mi], bh);
                }
            }
        }
    }

    const int gr0 = lane >> 2;
    const int gc0 = (lane & 3) * 2;
    #pragma unroll
    for (int mi = 0; mi < 2; mi++) {
        #pragma unroll
        for (int nj = 0; nj < 8; nj++) {
            int cc = warp_n * 64 + nj * 8 + gc0;
            int r1 = row0 + warp_m * 32 + mi * 16 + gr0;
            if (r1 < nrows) {
                __half2 h = __floats2half2_rn(acc[mi][nj][0], acc[mi][nj][1]);
                *(__half2*)&XWH_dst[(size_t)r1 * HD + cc] = h;
            }
            int r2 = r1 + 8;
            if (r2 < nrows) {
                __half2 h = __floats2half2_rn(acc[mi][nj][2], acc[mi][nj][3]);
                *(__half2*)&XWH_dst[(size_t)r2 * HD + cc] = h;
            }
        }
    }
}

// ---------------- final aggregation (layer 2) -------------------------------
__global__ void __launch_bounds__(256)
aggregate_kernel(const float* __restrict__ bias,
                 const __half* __restrict__ xwh,
                 float* __restrict__ out, int n)
{
    int node = blockIdx.x * 8 + (threadIdx.x >> 5);
    int lane = threadIdx.x & 31;
    if (node >= n) return;
    float4 acc = agg_node(node, lane, bias, xwh);
    ((float4*)(out + (size_t)node * HD))[lane] = acc;
}

// ---------------- launch ----------------------------------------------------
extern "C" void kernel_launch(void* const* d_in, const int* in_sizes, int n_in,
                              void* d_out, int out_size) {
    const float* emb = (const float*)d_in[0];
    const int*   ew  = (const int*)d_in[1];   // width detected on device
    const float* W1  = (const float*)d_in[2];
    const float* b1  = (const float*)d_in[3];
    const float* W2  = (const float*)d_in[4];
    const float* b2  = (const float*)d_in[5];
    float* out = (float*)d_out;

    const int nrows = in_sizes[0] / HD;       // 50000
    const int E     = in_sizes[1] / 2;        // 600000

    __half *xwh_p, *xwh2_p;
    cudaGetSymbolAddress((void**)&xwh_p,  g_xwh);
    cudaGetSymbolAddress((void**)&xwh2_p, g_xwh2);

    cudaFuncSetAttribute(gcn_gemm, cudaFuncAttributeMaxDynamicSharedMemorySize,
                         GEMM_SMEM_BYTES);
    cudaFuncSetAttribute(gcn_agg_gemm, cudaFuncAttributeMaxDynamicSharedMemorySize,
                         FUSED_SMEM_BYTES);

    static cudaStream_t s_side = nullptr;
    static cudaEvent_t  s_ev0 = nullptr, s_ev1 = nullptr;
    if (s_side == nullptr) {
        cudaStreamCreateWithFlags(&s_side, cudaStreamNonBlocking);
        cudaEventCreateWithFlags(&s_ev0, cudaEventDisableTiming);
        cudaEventCreateWithFlags(&s_ev1, cudaEventDisableTiming);
    }

    const int nb_nodes = (nrows + 255) / 256;   // 196
    const int nb_edges = (E + 255) / 256;       // 2344
    const int nb_gemm  = (nrows + 127) / 128;   // 391
    const int nb_agg   = (nrows + 7) / 8;       // 6250

    // ---- fork: layer-1 GEMM on side stream, CSR build on main stream ----
    cudaEventRecord(s_ev0, 0);
    cudaStreamWaitEvent(s_side, s_ev0, 0);
    gcn_gemm<<<nb_gemm, 256, GEMM_SMEM_BYTES, s_side>>>(emb, W1, xwh_p, nrows);
    cudaEventRecord(s_ev1, s_side);

    initdetect_kernel<<<nb_nodes, 256>>>(ew, nrows);
    hist_kernel<<<nb_edges, 256>>>(ew, E);
    scanM_kernel<<<nb_nodes, 256>>>(nrows);
    fill_kernel<<<nb_edges, 256>>>(ew, E);

    // ---- join, then fused tail ----
    cudaStreamWaitEvent(0, s_ev1, 0);
    gcn_agg_gemm<<<nb_gemm, 256, FUSED_SMEM_BYTES>>>(b1, W2, xwh_p, xwh2_p, nrows);
    aggregate_kernel<<<nb_agg, 256>>>(b2, xwh2_p, out, nrows);
}

// round 16
// speedup vs baseline: 1.2543x; 1.2543x over previous
#include <cuda_runtime.h>
#include <cuda_fp16.h>
#include <cuda_bf16.h>
#include <cstdint>

#define N_NODES 50000
#define HD 128
#define E_MAX 600000

// ---------------- scratch (device globals; no dynamic allocation) ----------
__device__ float  g_dis[N_NODES];                 // rsqrt(degree incl. self-loop)
__device__ int    g_cnt[N_NODES];                 // in-degree histogram
__device__ int2   g_seg[N_NODES];                 // (beg, deg) of node's segment
__device__ int    g_cursor[N_NODES];              // fill cursors
__device__ int    g_total;                        // ticket counter (reset by fill)
__device__ int2   g_csr[E_MAX];                   // packed (src, norm), segment-grouped
__device__ __half g_xwh[(size_t)N_NODES * HD];    // x @ W^T (fp16)
__device__ float  g_h1[(size_t)N_NODES * HD];     // layer-1 output (fp32)
__device__ int    g_is64;                         // 1 if edge_index stored as int64

struct __align__(8) h4 { __half2 a, b; };

// ---------------- init + dtype detect (merged) ------------------------------
__global__ void initdetect_kernel(const int* __restrict__ ew, int n) {
    int i = blockIdx.x * blockDim.x + threadIdx.x;
    if (i < n) g_cnt[i] = 0;
    if (blockIdx.x == 0) {
        __shared__ int found;
        if (threadIdx.x == 0) found = 0;
        __syncthreads();
        int f = 0;
        for (int j = threadIdx.x; j < 2048; j += blockDim.x)
            if (ew[2 * j + 1] != 0) f = 1;
        if (f) atomicOr(&found, 1);
        __syncthreads();
        if (threadIdx.x == 0) g_is64 = found ? 0 : 1;
    }
}

__global__ void hist_kernel(const int* __restrict__ ew, int E) {
    int e = blockIdx.x * blockDim.x + threadIdx.x;
    if (e >= E) return;
    int d = g_is64 ? ew[2 * (E + e)] : ew[E + e];
    atomicAdd(&g_cnt[d], 1);
}

// ---- single-launch segment assignment (ticket scan) ------------------------
__global__ void scanM_kernel(int n) {
    __shared__ int sm[256];
    __shared__ int base_sh;
    int i = blockIdx.x * 256 + threadIdx.x;
    int v = (i < n) ? g_cnt[i] : 0;
    if (i < n) g_dis[i] = rsqrtf((float)(v + 1));
    sm[threadIdx.x] = v;
    __syncthreads();
    #pragma unroll
    for (int off = 1; off < 256; off <<= 1) {
        int t = (threadIdx.x >= off) ? sm[threadIdx.x - off] : 0;
        __syncthreads();
        sm[threadIdx.x] += t;
        __syncthreads();
    }
    if (threadIdx.x == 255) base_sh = atomicAdd(&g_total, sm[255]);
    __syncthreads();
    if (i < n) {
        int beg = base_sh + sm[threadIdx.x] - v;
        g_seg[i] = make_int2(beg, v);
        g_cursor[i] = beg;
    }
}

__global__ void fill_kernel(const int* __restrict__ ew, int E) {
    if (blockIdx.x == 0 && threadIdx.x == 0) g_total = 0;   // reset for replays
    int e = blockIdx.x * blockDim.x + threadIdx.x;
    if (e >= E) return;
    int s, d;
    if (g_is64) { s = ew[2 * e]; d = ew[2 * (E + e)]; }
    else        { s = ew[e];     d = ew[E + e]; }
    int pos = atomicAdd(&g_cursor[d], 1);
    float nm = g_dis[s] * g_dis[d];
    g_csr[pos] = make_int2(s, __float_as_int(nm));
}

// =========== tensor-core GEMM: XWH = fp16(X @ W^T), bf16 split ============
#define GEMM_SMEM_BYTES 65536
#define AHI_OFF 0
#define ALO_OFF 16384
#define BHI_OFF 32768
#define BLO_OFF 49152

static __device__ __forceinline__ uint32_t smem_u32(const void* p) {
    uint32_t a;
    asm("{ .reg .u64 t; cvta.to.shared.u64 t, %1; cvt.u32.u64 %0, t; }"
        : "=r"(a) : "l"(p));
    return a;
}

static __device__ __forceinline__ uint32_t sw_off(int r, int c) {
    return (uint32_t)(r * 128 + (((c) << 4) ^ ((r & 7) << 4)));
}

static __device__ __forceinline__ void split_pair(float x, float y,
                                                  uint32_t& hi, uint32_t& lo) {
    __nv_bfloat162 h = __floats2bfloat162_rn(x, y);
    __nv_bfloat162 l = __floats2bfloat162_rn(x - __bfloat162float(h.x),
                                             y - __bfloat162float(h.y));
    hi = *reinterpret_cast<uint32_t*>(&h);
    lo = *reinterpret_cast<uint32_t*>(&l);
}

#define LDSM_X4(r, addr) \
    asm volatile("ldmatrix.sync.aligned.m8n8.x4.shared.b16 {%0,%1,%2,%3}, [%4];" \
                 : "=r"((r)[0]), "=r"((r)[1]), "=r"((r)[2]), "=r"((r)[3]) : "r"(addr))
#define LDSM_X2(r, addr) \
    asm volatile("ldmatrix.sync.aligned.m8n8.x2.shared.b16 {%0,%1}, [%2];" \
                 : "=r"((r)[0]), "=r"((r)[1]) : "r"(addr))
#define MMA_BF16(d, a, b) \
    asm volatile("mma.sync.aligned.m16n8k16.row.col.f32.bf16.bf16.f32 " \
                 "{%0,%1,%2,%3}, {%4,%5,%6,%7}, {%8,%9}, {%0,%1,%2,%3};" \
                 : "+f"((d)[0]), "+f"((d)[1]), "+f"((d)[2]), "+f"((d)[3]) \
                 : "r"((a)[0]), "r"((a)[1]), "r"((a)[2]), "r"((a)[3]), \
                   "r"((b)[0]), "r"((b)[1]))

__global__ void __launch_bounds__(256, 2)
gcn_gemm(const float* __restrict__ X, const float* __restrict__ W,
         __half* __restrict__ XWH, int nrows)
{
    extern __shared__ char smem[];
    const uint32_t smb = smem_u32(smem);
    const int tid = threadIdx.x;
    const int lane = tid & 31;
    const int wid = tid >> 5;
    const int warp_m = wid & 3;
    const int warp_n = wid >> 2;
    const int row0 = blockIdx.x * 128;

    float acc[2][8][4];
    #pragma unroll
    for (int mi = 0; mi < 2; mi++)
        #pragma unroll
        for (int nj = 0; nj < 8; nj++)
            #pragma unroll
            for (int q = 0; q < 4; q++) acc[mi][nj][q] = 0.f;

    const int arow = lane & 15;
    const int akh  = lane >> 4;
    const int brow = lane & 7;
    const int bkh  = (lane >> 3) & 1;

    #pragma unroll
    for (int t = 0; t < 2; t++) {
        const int k0 = t * 64;

        #pragma unroll
        for (int it = 0; it < 4; it++) {
            int id = tid + 256 * it;
            int r = id >> 3, c8 = id & 7;
            uint32_t so = sw_off(r, c8);
            int gr = row0 + r;
            float4 xa = make_float4(0.f, 0.f, 0.f, 0.f), xb = xa;
            if (gr < nrows) {
                const float4* xp = (const float4*)(X + (size_t)gr * HD + k0 + c8 * 8);
                xa = xp[0]; xb = xp[1];
            }
            uint4 hi4, lo4;
            split_pair(xa.x, xa.y, hi4.x, lo4.x);
            split_pair(xa.z, xa.w, hi4.y, lo4.y);
            split_pair(xb.x, xb.y, hi4.z, lo4.z);
            split_pair(xb.z, xb.w, hi4.w, lo4.w);
            *(uint4*)(smem + AHI_OFF + so) = hi4;
            *(uint4*)(smem + ALO_OFF + so) = lo4;
            const float4* wp = (const float4*)(W + (size_t)r * HD + k0 + c8 * 8);
            float4 wa = wp[0], wb = wp[1];
            split_pair(wa.x, wa.y, hi4.x, lo4.x);
            split_pair(wa.z, wa.w, hi4.y, lo4.y);
            split_pair(wb.x, wb.y, hi4.z, lo4.z);
            split_pair(wb.z, wb.w, hi4.w, lo4.w);
            *(uint4*)(smem + BHI_OFF + so) = hi4;
            *(uint4*)(smem + BLO_OFF + so) = lo4;
        }
        __syncthreads();

        #pragma unroll
        for (int kc = 0; kc < 4; kc++) {
            uint32_t ahi[2][4], alo[2][4];
            #pragma unroll
            for (int mi = 0; mi < 2; mi++) {
                int rr = warp_m * 32 + mi * 16 + arow;
                uint32_t off = sw_off(rr, 2 * kc + akh);
                LDSM_X4(ahi[mi], smb + AHI_OFF + off);
                LDSM_X4(alo[mi], smb + ALO_OFF + off);
            }
            #pragma unroll
            for (int nj = 0; nj < 8; nj++) {
                int nr = warp_n * 64 + nj * 8 + brow;
                uint32_t boff = sw_off(nr, 2 * kc + bkh);
                uint32_t bh[2], bl[2];
                LDSM_X2(bh, smb + BHI_OFF + boff);
                LDSM_X2(bl, smb + BLO_OFF + boff);
                #pragma unroll
                for (int mi = 0; mi < 2; mi++) {
                    MMA_BF16(acc[mi][nj], ahi[mi], bh);
                    MMA_BF16(acc[mi][nj], ahi[mi], bl);
                    MMA_BF16(acc[mi][nj], alo[mi], bh);
                }
            }
        }
        __syncthreads();
    }

    const int gr0 = lane >> 2;
    const int gc0 = (lane & 3) * 2;
    #pragma unroll
    for (int mi = 0; mi < 2; mi++) {
        #pragma unroll
        for (int nj = 0; nj < 8; nj++) {
            int cc = warp_n * 64 + nj * 8 + gc0;
            int r1 = row0 + warp_m * 32 + mi * 16 + gr0;
            if (r1 < nrows) {
                __half2 h = __floats2half2_rn(acc[mi][nj][0], acc[mi][nj][1]);
                *(__half2*)&XWH[(size_t)r1 * HD + cc] = h;
            }
            int r2 = r1 + 8;
            if (r2 < nrows) {
                __half2 h = __floats2half2_rn(acc[mi][nj][2], acc[mi][nj][3]);
                *(__half2*)&XWH[(size_t)r2 * HD + cc] = h;
            }
        }
    }
}

// ---------------- aggregation ------------------------------------------------
// out[d] = b + dis[d]^2 * xwh[d] + sum norm_e * xwh[src_e]
// Lane-parallel edge fetch: lane i preloads edge beg+i (one coalesced load),
// shfl-broadcast per edge -> all gathers independent (MLP ~= deg).
__global__ void __launch_bounds__(256)
aggregate_kernel(const float* __restrict__ bias,
                 const __half* __restrict__ xwh,
                 float* __restrict__ out, int n)
{
    int node = blockIdx.x * 8 + (threadIdx.x >> 5);
    int lane = threadIdx.x & 31;
    if (node >= n) return;

    int2 seg = g_seg[node];
    int beg = seg.x;
    int deg = seg.y;

    float ds = g_dis[node];
    float sc = ds * ds;
    h4 hs = ((const h4*)(xwh + (size_t)node * HD))[lane];
    float2 s0 = __half22float2(hs.a), s1 = __half22float2(hs.b);
    float4 b4 = ((const float4*)bias)[lane];
    float4 acc;
    acc.x = fmaf(sc, s0.x, b4.x);
    acc.y = fmaf(sc, s0.y, b4.y);
    acc.z = fmaf(sc, s1.x, b4.z);
    acc.w = fmaf(sc, s1.y, b4.w);

    int2 my_e = make_int2(0, 0);
    if (lane < deg) my_e = g_csr[beg + lane];
    int m = min(deg, 32);
    #pragma unroll 4
    for (int j = 0; j < m; j++) {
        int   s  = __shfl_sync(0xffffffffu, my_e.x, j);
        float nm = __int_as_float(__shfl_sync(0xffffffffu, my_e.y, j));
        h4 hv = ((const h4*)(xwh + (size_t)s * HD))[lane];
        float2 fa = __half22float2(hv.a), fb = __half22float2(hv.b);
        acc.x = fmaf(nm, fa.x, acc.x); acc.y = fmaf(nm, fa.y, acc.y);
        acc.z = fmaf(nm, fb.x, acc.z); acc.w = fmaf(nm, fb.y, acc.w);
    }
    // rare tail: deg > 32
    for (int p = beg + 32; p < beg + deg; p++) {
        int2 e = g_csr[p];
        h4 hv = ((const h4*)(xwh + (size_t)e.x * HD))[lane];
        float nm = __int_as_float(e.y);
        float2 fa = __half22float2(hv.a), fb = __half22float2(hv.b);
        acc.x = fmaf(nm, fa.x, acc.x); acc.y = fmaf(nm, fa.y, acc.y);
        acc.z = fmaf(nm, fb.x, acc.z); acc.w = fmaf(nm, fb.y, acc.w);
    }

    ((float4*)(out + (size_t)node * HD))[lane] = acc;
}

// ---------------- launch ----------------------------------------------------
extern "C" void kernel_launch(void* const* d_in, const int* in_sizes, int n_in,
                              void* d_out, int out_size) {
    const float* emb = (const float*)d_in[0];
    const int*   ew  = (const int*)d_in[1];   // width detected on device
    const float* W1  = (const float*)d_in[2];
    const float* b1  = (const float*)d_in[3];
    const float* W2  = (const float*)d_in[4];
    const float* b2  = (const float*)d_in[5];
    float* out = (float*)d_out;

    const int nrows = in_sizes[0] / HD;       // 50000
    const int E     = in_sizes[1] / 2;        // 600000

    float* h1_p;
    __half* xwh_p;
    cudaGetSymbolAddress((void**)&xwh_p, g_xwh);
    cudaGetSymbolAddress((void**)&h1_p,  g_h1);

    cudaFuncSetAttribute(gcn_gemm, cudaFuncAttributeMaxDynamicSharedMemorySize,
                         GEMM_SMEM_BYTES);

    // Side stream + events (created once on the first, non-captured call).
    static cudaStream_t s_side = nullptr;
    static cudaEvent_t  s_ev0 = nullptr, s_ev1 = nullptr;
    if (s_side == nullptr) {
        cudaStreamCreateWithFlags(&s_side, cudaStreamNonBlocking);
        cudaEventCreateWithFlags(&s_ev0, cudaEventDisableTiming);
        cudaEventCreateWithFlags(&s_ev1, cudaEventDisableTiming);
    }

    const int nb_nodes = (nrows + 255) / 256;   // 196
    const int nb_edges = (E + 255) / 256;       // 2344
    const int nb_gemm  = (nrows + 127) / 128;   // 391
    const int nb_agg   = (nrows + 7) / 8;       // 6250

    // ---- fork: layer-1 GEMM on side stream, CSR build on main stream ----
    cudaEventRecord(s_ev0, 0);
    cudaStreamWaitEvent(s_side, s_ev0, 0);
    gcn_gemm<<<nb_gemm, 256, GEMM_SMEM_BYTES, s_side>>>(emb, W1, xwh_p, nrows);
    cudaEventRecord(s_ev1, s_side);

    initdetect_kernel<<<nb_nodes, 256>>>(ew, nrows);
    hist_kernel<<<nb_edges, 256>>>(ew, E);
    scanM_kernel<<<nb_nodes, 256>>>(nrows);
    fill_kernel<<<nb_edges, 256>>>(ew, E);

    // ---- join, then serial tail ----
    cudaStreamWaitEvent(0, s_ev1, 0);
    aggregate_kernel<<<nb_agg, 256>>>(b1, xwh_p, h1_p, nrows);
    gcn_gemm<<<nb_gemm, 256, GEMM_SMEM_BYTES>>>(h1_p, W2, xwh_p, nrows);
    aggregate_kernel<<<nb_agg, 256>>>(b2, xwh_p, out, nrows);
}

// round 17
// speedup vs baseline: 1.4020x; 1.1178x over previous
#include <cuda_runtime.h>
#include <cuda_fp16.h>
#include <cuda_bf16.h>
#include <cstdint>

#define N_NODES 50000
#define HD 128
#define E_MAX 600000

// ---------------- scratch (device globals; no dynamic allocation) ----------
__device__ float  g_dis[N_NODES];                 // rsqrt(degree incl. self-loop)
__device__ int    g_cnt[N_NODES];                 // in-degree histogram (zero-restored by fill)
__device__ int2   g_seg[N_NODES];                 // (beg, deg) of node's segment
__device__ int    g_cursor[N_NODES];              // fill cursors
__device__ int    g_total;                        // ticket counter (reset by fill)
__device__ int2   g_csr[E_MAX];                   // packed (src, norm), segment-grouped
__device__ __half g_xwh[(size_t)N_NODES * HD];    // layer-1 x @ W^T (fp16)
__device__ __half g_h1h[(size_t)N_NODES * HD];    // layer-1 output h1 (fp16)
__device__ __half g_xwh2[(size_t)N_NODES * HD];   // layer-2 h1 @ W2^T (fp16)
__device__ int    g_is64;                         // 1 if edge_index stored as int64

struct __align__(8) h4 { __half2 a, b; };

// ---------------- dtype detect (1 block) -------------------------------------
// int64 little-endian => odd 32-bit words of the first 2048 logical elements
// are all zero (random int32 indices make that impossible). In-bounds for both.
__global__ void detect_kernel(const int* __restrict__ ew) {
    __shared__ int found;
    if (threadIdx.x == 0) found = 0;
    __syncthreads();
    int f = 0;
    for (int j = threadIdx.x; j < 2048; j += blockDim.x)
        if (ew[2 * j + 1] != 0) f = 1;
    if (f) atomicOr(&found, 1);
    __syncthreads();
    if (threadIdx.x == 0) g_is64 = found ? 0 : 1;
}

__global__ void hist_kernel(const int* __restrict__ ew, int E) {
    int e = blockIdx.x * blockDim.x + threadIdx.x;
    if (e >= E) return;
    int d = g_is64 ? ew[2 * (E + e)] : ew[E + e];
    atomicAdd(&g_cnt[d], 1);
}

// ---- single-launch segment assignment (ticket scan) ------------------------
__global__ void scanM_kernel(int n) {
    __shared__ int sm[256];
    __shared__ int base_sh;
    int i = blockIdx.x * 256 + threadIdx.x;
    int v = (i < n) ? g_cnt[i] : 0;
    if (i < n) g_dis[i] = rsqrtf((float)(v + 1));
    sm[threadIdx.x] = v;
    __syncthreads();
    #pragma unroll
    for (int off = 1; off < 256; off <<= 1) {
        int t = (threadIdx.x >= off) ? sm[threadIdx.x - off] : 0;
        __syncthreads();
        sm[threadIdx.x] += t;
        __syncthreads();
    }
    if (threadIdx.x == 255) base_sh = atomicAdd(&g_total, sm[255]);
    __syncthreads();
    if (i < n) {
        int beg = base_sh + sm[threadIdx.x] - v;
        g_seg[i] = make_int2(beg, v);
        g_cursor[i] = beg;
    }
}

// fill CSR; also restores g_total and g_cnt to zero for the next call/replay
// (scanM has already consumed both; first call relies on static zero-init).
__global__ void fill_kernel(const int* __restrict__ ew, int E, int n) {
    if (blockIdx.x == 0 && threadIdx.x == 0) g_total = 0;
    int e = blockIdx.x * blockDim.x + threadIdx.x;
    if (e < n) g_cnt[e] = 0;
    if (e >= E) return;
    int s, d;
    if (g_is64) { s = ew[2 * e]; d = ew[2 * (E + e)]; }
    else        { s = ew[e];     d = ew[E + e]; }
    int pos = atomicAdd(&g_cursor[d], 1);
    float nm = g_dis[s] * g_dis[d];
    g_csr[pos] = make_int2(s, __float_as_int(nm));
}

// ---------------- shared GEMM helpers ---------------------------------------
static __device__ __forceinline__ uint32_t smem_u32(const void* p) {
    uint32_t a;
    asm("{ .reg .u64 t; cvta.to.shared.u64 t, %1; cvt.u32.u64 %0, t; }"
        : "=r"(a) : "l"(p));
    return a;
}
static __device__ __forceinline__ uint32_t sw_off(int r, int c) {
    return (uint32_t)(r * 128 + (((c) << 4) ^ ((r & 7) << 4)));
}
static __device__ __forceinline__ void split_pair(float x, float y,
                                                  uint32_t& hi, uint32_t& lo) {
    __nv_bfloat162 h = __floats2bfloat162_rn(x, y);
    __nv_bfloat162 l = __floats2bfloat162_rn(x - __bfloat162float(h.x),
                                             y - __bfloat162float(h.y));
    hi = *reinterpret_cast<uint32_t*>(&h);
    lo = *reinterpret_cast<uint32_t*>(&l);
}

#define LDSM_X4(r, addr) \
    asm volatile("ldmatrix.sync.aligned.m8n8.x4.shared.b16 {%0,%1,%2,%3}, [%4];" \
                 : "=r"((r)[0]), "=r"((r)[1]), "=r"((r)[2]), "=r"((r)[3]) : "r"(addr))
#define LDSM_X2(r, addr) \
    asm volatile("ldmatrix.sync.aligned.m8n8.x2.shared.b16 {%0,%1}, [%2];" \
                 : "=r"((r)[0]), "=r"((r)[1]) : "r"(addr))
#define MMA_BF16(d, a, b) \
    asm volatile("mma.sync.aligned.m16n8k16.row.col.f32.bf16.bf16.f32 " \
                 "{%0,%1,%2,%3}, {%4,%5,%6,%7}, {%8,%9}, {%0,%1,%2,%3};" \
                 : "+f"((d)[0]), "+f"((d)[1]), "+f"((d)[2]), "+f"((d)[3]) \
                 : "r"((a)[0]), "r"((a)[1]), "r"((a)[2]), "r"((a)[3]), \
                   "r"((b)[0]), "r"((b)[1]))
#define MMA_F16(d, a, b) \
    asm volatile("mma.sync.aligned.m16n8k16.row.col.f32.f16.f16.f32 " \
                 "{%0,%1,%2,%3}, {%4,%5,%6,%7}, {%8,%9}, {%0,%1,%2,%3};" \
                 : "+f"((d)[0]), "+f"((d)[1]), "+f"((d)[2]), "+f"((d)[3]) \
                 : "r"((a)[0]), "r"((a)[1]), "r"((a)[2]), "r"((a)[3]), \
                   "r"((b)[0]), "r"((b)[1]))

// ---------------- per-node aggregation (float4 over lane's 4 cols) ----------
static __device__ __forceinline__ float4
agg_node(int node, int lane, const float* __restrict__ bias,
         const __half* __restrict__ xwh)
{
    int2 seg = g_seg[node];
    int beg = seg.x, end = seg.x + seg.y;
    float ds = g_dis[node];
    float sc = ds * ds;
    h4 hs = ((const h4*)(xwh + (size_t)node * HD))[lane];
    float2 s0 = __half22float2(hs.a), s1 = __half22float2(hs.b);
    float4 b4 = ((const float4*)bias)[lane];
    float4 acc;
    acc.x = fmaf(sc, s0.x, b4.x);
    acc.y = fmaf(sc, s0.y, b4.y);
    acc.z = fmaf(sc, s1.x, b4.z);
    acc.w = fmaf(sc, s1.y, b4.w);
    int p = beg;
    for (; p + 4 <= end; p += 4) {
        int2 e0 = g_csr[p + 0];
        int2 e1 = g_csr[p + 1];
        int2 e2 = g_csr[p + 2];
        int2 e3 = g_csr[p + 3];
        h4 h0 = ((const h4*)(xwh + (size_t)e0.x * HD))[lane];
        h4 h1 = ((const h4*)(xwh + (size_t)e1.x * HD))[lane];
        h4 h2 = ((const h4*)(xwh + (size_t)e2.x * HD))[lane];
        h4 h3 = ((const h4*)(xwh + (size_t)e3.x * HD))[lane];
        float n0 = __int_as_float(e0.y), n1 = __int_as_float(e1.y);
        float n2 = __int_as_float(e2.y), n3 = __int_as_float(e3.y);
        float2 a0 = __half22float2(h0.a), c0 = __half22float2(h0.b);
        float2 a1 = __half22float2(h1.a), c1 = __half22float2(h1.b);
        float2 a2 = __half22float2(h2.a), c2 = __half22float2(h2.b);
        float2 a3 = __half22float2(h3.a), c3 = __half22float2(h3.b);
        acc.x = fmaf(n0, a0.x, acc.x); acc.y = fmaf(n0, a0.y, acc.y);
        acc.z = fmaf(n0, c0.x, acc.z); acc.w = fmaf(n0, c0.y, acc.w);
        acc.x = fmaf(n1, a1.x, acc.x); acc.y = fmaf(n1, a1.y, acc.y);
        acc.z = fmaf(n1, c1.x, acc.z); acc.w = fmaf(n1, c1.y, acc.w);
        acc.x = fmaf(n2, a2.x, acc.x); acc.y = fmaf(n2, a2.y, acc.y);
        acc.z = fmaf(n2, c2.x, acc.z); acc.w = fmaf(n2, c2.y, acc.w);
        acc.x = fmaf(n3, a3.x, acc.x); acc.y = fmaf(n3, a3.y, acc.y);
        acc.z = fmaf(n3, c3.x, acc.z); acc.w = fmaf(n3, c3.y, acc.w);
    }
    for (; p < end; p++) {
        int2 e = g_csr[p];
        h4 hv = ((const h4*)(xwh + (size_t)e.x * HD))[lane];
        float nm = __int_as_float(e.y);
        float2 fa = __half22float2(hv.a), fb = __half22float2(hv.b);
        acc.x = fmaf(nm, fa.x, acc.x); acc.y = fmaf(nm, fa.y, acc.y);
        acc.z = fmaf(nm, fb.x, acc.z); acc.w = fmaf(nm, fb.y, acc.w);
    }
    return acc;
}

// =========== layer-1 GEMM: XWH = fp16(X @ W1^T), bf16 2-term split ========
#define GEMM_SMEM_BYTES 65536
#define AHI_OFF 0
#define ALO_OFF 16384
#define BHI_OFF 32768
#define BLO_OFF 49152

__global__ void __launch_bounds__(256, 2)
gcn_gemm(const float* __restrict__ X, const float* __restrict__ W,
         __half* __restrict__ XWH, int nrows)
{
    extern __shared__ char smem[];
    const uint32_t smb = smem_u32(smem);
    const int tid = threadIdx.x;
    const int lane = tid & 31;
    const int wid = tid >> 5;
    const int warp_m = wid & 3;
    const int warp_n = wid >> 2;
    const int row0 = blockIdx.x * 128;

    float acc[2][8][4];
    #pragma unroll
    for (int mi = 0; mi < 2; mi++)
        #pragma unroll
        for (int nj = 0; nj < 8; nj++)
            #pragma unroll
            for (int q = 0; q < 4; q++) acc[mi][nj][q] = 0.f;

    const int arow = lane & 15;
    const int akh  = lane >> 4;
    const int brow = lane & 7;
    const int bkh  = (lane >> 3) & 1;

    #pragma unroll
    for (int t = 0; t < 2; t++) {
        const int k0 = t * 64;
        #pragma unroll
        for (int it = 0; it < 4; it++) {
            int id = tid + 256 * it;
            int r = id >> 3, c8 = id & 7;
            uint32_t so = sw_off(r, c8);
            int gr = row0 + r;
            float4 xa = make_float4(0.f, 0.f, 0.f, 0.f), xb = xa;
            if (gr < nrows) {
                const float4* xp = (const float4*)(X + (size_t)gr * HD + k0 + c8 * 8);
                xa = xp[0]; xb = xp[1];
            }
            uint4 hi4, lo4;
            split_pair(xa.x, xa.y, hi4.x, lo4.x);
            split_pair(xa.z, xa.w, hi4.y, lo4.y);
            split_pair(xb.x, xb.y, hi4.z, lo4.z);
            split_pair(xb.z, xb.w, hi4.w, lo4.w);
            *(uint4*)(smem + AHI_OFF + so) = hi4;
            *(uint4*)(smem + ALO_OFF + so) = lo4;
            const float4* wp = (const float4*)(W + (size_t)r * HD + k0 + c8 * 8);
            float4 wa = wp[0], wb = wp[1];
            split_pair(wa.x, wa.y, hi4.x, lo4.x);
            split_pair(wa.z, wa.w, hi4.y, lo4.y);
            split_pair(wb.x, wb.y, hi4.z, lo4.z);
            split_pair(wb.z, wb.w, hi4.w, lo4.w);
            *(uint4*)(smem + BHI_OFF + so) = hi4;
            *(uint4*)(smem + BLO_OFF + so) = lo4;
        }
        __syncthreads();

        #pragma unroll
        for (int kc = 0; kc < 4; kc++) {
            uint32_t ahi[2][4], alo[2][4];
            #pragma unroll
            for (int mi = 0; mi < 2; mi++) {
                int rr = warp_m * 32 + mi * 16 + arow;
                uint32_t off = sw_off(rr, 2 * kc + akh);
                LDSM_X4(ahi[mi], smb + AHI_OFF + off);
                LDSM_X4(alo[mi], smb + ALO_OFF + off);
            }
            #pragma unroll
            for (int nj = 0; nj < 8; nj++) {
                int nr = warp_n * 64 + nj * 8 + brow;
                uint32_t boff = sw_off(nr, 2 * kc + bkh);
                uint32_t bh[2], bl[2];
                LDSM_X2(bh, smb + BHI_OFF + boff);
                LDSM_X2(bl, smb + BLO_OFF + boff);
                #pragma unroll
                for (int mi = 0; mi < 2; mi++) {
                    MMA_BF16(acc[mi][nj], ahi[mi], bh);
                    MMA_BF16(acc[mi][nj], ahi[mi], bl);
                    MMA_BF16(acc[mi][nj], alo[mi], bh);
                }
            }
        }
        __syncthreads();
    }

    const int gr0 = lane >> 2;
    const int gc0 = (lane & 3) * 2;
    #pragma unroll
    for (int mi = 0; mi < 2; mi++) {
        #pragma unroll
        for (int nj = 0; nj < 8; nj++) {
            int cc = warp_n * 64 + nj * 8 + gc0;
            int r1 = row0 + warp_m * 32 + mi * 16 + gr0;
            if (r1 < nrows) {
                __half2 h = __floats2half2_rn(acc[mi][nj][0], acc[mi][nj][1]);
                *(__half2*)&XWH[(size_t)r1 * HD + cc] = h;
            }
            int r2 = r1 + 8;
            if (r2 < nrows) {
                __half2 h = __floats2half2_rn(acc[mi][nj][2], acc[mi][nj][3]);
                *(__half2*)&XWH[(size_t)r2 * HD + cc] = h;
            }
        }
    }
}

// =========== layer-2 GEMM: XWH2 = fp16( H1(fp16) @ W2^T ), single pass ====
#define GEMM2_SMEM_BYTES 32768
#define A16_OFF 0
#define B16_OFF 16384

__global__ void __launch_bounds__(256, 2)
gcn_gemm_f16(const __half* __restrict__ A, const float* __restrict__ W,
             __half* __restrict__ XWH, int nrows)
{
    extern __shared__ char smem[];
    const uint32_t smb = smem_u32(smem);
    const int tid = threadIdx.x;
    const int lane = tid & 31;
    const int wid = tid >> 5;
    const int warp_m = wid & 3;
    const int warp_n = wid >> 2;
    const int row0 = blockIdx.x * 128;

    float acc[2][8][4];
    #pragma unroll
    for (int mi = 0; mi < 2; mi++)
        #pragma unroll
        for (int nj = 0; nj < 8; nj++)
            #pragma unroll
            for (int q = 0; q < 4; q++) acc[mi][nj][q] = 0.f;

    const int arow = lane & 15;
    const int akh  = lane >> 4;
    const int brow = lane & 7;
    const int bkh  = (lane >> 3) & 1;

    #pragma unroll
    for (int t = 0; t < 2; t++) {
        const int k0 = t * 64;
        if (t > 0) __syncthreads();
        // A tile: fp16 rows copied directly (16B = 8 halves per chunk)
        #pragma unroll
        for (int it = 0; it < 4; it++) {
            int id = tid + 256 * it;
            int r = id >> 3, c8 = id & 7;
            uint32_t so = sw_off(r, c8);
            int gr = row0 + r;
            uint4 av = make_uint4(0u, 0u, 0u, 0u);
            if (gr < nrows)
                av = *(const uint4*)(A + (size_t)gr * HD + k0 + c8 * 8);
            *(uint4*)(smem + A16_OFF + so) = av;
            // B tile: W fp32 -> fp16
            const float4* wp = (const float4*)(W + (size_t)r * HD + k0 + c8 * 8);
            float4 wa = wp[0], wb = wp[1];
            uint4 bv;
            __half2 t0 = __floats2half2_rn(wa.x, wa.y);
            __half2 t1 = __floats2half2_rn(wa.z, wa.w);
            __half2 t2 = __floats2half2_rn(wb.x, wb.y);
            __half2 t3 = __floats2half2_rn(wb.z, wb.w);
            bv.x = *reinterpret_cast<uint32_t*>(&t0);
            bv.y = *reinterpret_cast<uint32_t*>(&t1);
            bv.z = *reinterpret_cast<uint32_t*>(&t2);
            bv.w = *reinterpret_cast<uint32_t*>(&t3);
            *(uint4*)(smem + B16_OFF + so) = bv;
        }
        __syncthreads();

        #pragma unroll
        for (int kc = 0; kc < 4; kc++) {
            uint32_t a16[2][4];
            #pragma unroll
            for (int mi = 0; mi < 2; mi++) {
                int rr = warp_m * 32 + mi * 16 + arow;
                uint32_t off = sw_off(rr, 2 * kc + akh);
                LDSM_X4(a16[mi], smb + A16_OFF + off);
            }
            #pragma unroll
            for (int nj = 0; nj < 8; nj++) {
                int nr = warp_n * 64 + nj * 8 + brow;
                uint32_t boff = sw_off(nr, 2 * kc + bkh);
                uint32_t b16[2];
                LDSM_X2(b16, smb + B16_OFF + boff);
                #pragma unroll
                for (int mi = 0; mi < 2; mi++)
                    MMA_F16(acc[mi][nj], a16[mi], b16);
            }
        }
    }

    const int gr0 = lane >> 2;
    const int gc0 = (lane & 3) * 2;
    #pragma unroll
    for (int mi = 0; mi < 2; mi++) {
        #pragma unroll
        for (int nj = 0; nj < 8; nj++) {
            int cc = warp_n * 64 + nj * 8 + gc0;
            int r1 = row0 + warp_m * 32 + mi * 16 + gr0;
            if (r1 < nrows) {
                __half2 h = __floats2half2_rn(acc[mi][nj][0], acc[mi][nj][1]);
                *(__half2*)&XWH[(size_t)r1 * HD + cc] = h;
            }
            int r2 = r1 + 8;
            if (r2 < nrows) {
                __half2 h = __floats2half2_rn(acc[mi][nj][2], acc[mi][nj][3]);
                *(__half2*)&XWH[(size_t)r2 * HD + cc] = h;
            }
        }
    }
}

// ---------------- aggregations ----------------------------------------------
// layer-1: writes h1 as fp16 (input to the fp16 layer-2 GEMM)
__global__ void __launch_bounds__(256)
aggregate_h16_kernel(const float* __restrict__ bias,
                     const __half* __restrict__ xwh,
                     __half* __restrict__ out, int n)
{
    int node = blockIdx.x * 8 + (threadIdx.x >> 5);
    int lane = threadIdx.x & 31;
    if (node >= n) return;
    float4 acc = agg_node(node, lane, bias, xwh);
    h4 h;
    h.a = __floats2half2_rn(acc.x, acc.y);
    h.b = __floats2half2_rn(acc.z, acc.w);
    ((h4*)(out + (size_t)node * HD))[lane] = h;
}

// layer-2: writes final fp32 output
__global__ void __launch_bounds__(256)
aggregate_kernel(const float* __restrict__ bias,
                 const __half* __restrict__ xwh,
                 float* __restrict__ out, int n)
{
    int node = blockIdx.x * 8 + (threadIdx.x >> 5);
    int lane = threadIdx.x & 31;
    if (node >= n) return;
    float4 acc = agg_node(node, lane, bias, xwh);
    ((float4*)(out + (size_t)node * HD))[lane] = acc;
}

// ---------------- launch ----------------------------------------------------
extern "C" void kernel_launch(void* const* d_in, const int* in_sizes, int n_in,
                              void* d_out, int out_size) {
    const float* emb = (const float*)d_in[0];
    const int*   ew  = (const int*)d_in[1];   // width detected on device
    const float* W1  = (const float*)d_in[2];
    const float* b1  = (const float*)d_in[3];
    const float* W2  = (const float*)d_in[4];
    const float* b2  = (const float*)d_in[5];
    float* out = (float*)d_out;

    const int nrows = in_sizes[0] / HD;       // 50000
    const int E     = in_sizes[1] / 2;        // 600000

    __half *xwh_p, *h1h_p, *xwh2_p;
    cudaGetSymbolAddress((void**)&xwh_p,  g_xwh);
    cudaGetSymbolAddress((void**)&h1h_p,  g_h1h);
    cudaGetSymbolAddress((void**)&xwh2_p, g_xwh2);

    cudaFuncSetAttribute(gcn_gemm, cudaFuncAttributeMaxDynamicSharedMemorySize,
                         GEMM_SMEM_BYTES);
    cudaFuncSetAttribute(gcn_gemm_f16, cudaFuncAttributeMaxDynamicSharedMemorySize,
                         GEMM2_SMEM_BYTES);

    // Side stream + events (created once on the first, non-captured call).
    static cudaStream_t s_side = nullptr;
    static cudaEvent_t  s_ev0 = nullptr, s_ev1 = nullptr;
    if (s_side == nullptr) {
        cudaStreamCreateWithFlags(&s_side, cudaStreamNonBlocking);
        cudaEventCreateWithFlags(&s_ev0, cudaEventDisableTiming);
        cudaEventCreateWithFlags(&s_ev1, cudaEventDisableTiming);
    }

    const int nb_nodes = (nrows + 255) / 256;   // 196
    const int nb_edges = (E + 255) / 256;       // 2344
    const int nb_gemm  = (nrows + 127) / 128;   // 391
    const int nb_agg   = (nrows + 7) / 8;       // 6250

    // ---- fork: layer-1 GEMM on side stream, CSR build on main stream ----
    cudaEventRecord(s_ev0, 0);
    cudaStreamWaitEvent(s_side, s_ev0, 0);
    gcn_gemm<<<nb_gemm, 256, GEMM_SMEM_BYTES, s_side>>>(emb, W1, xwh_p, nrows);
    cudaEventRecord(s_ev1, s_side);

    detect_kernel<<<1, 256>>>(ew);
    hist_kernel<<<nb_edges, 256>>>(ew, E);
    scanM_kernel<<<nb_nodes, 256>>>(nrows);
    fill_kernel<<<nb_edges, 256>>>(ew, E, nrows);

    // ---- join, then serial tail ----
    cudaStreamWaitEvent(0, s_ev1, 0);
    aggregate_h16_kernel<<<nb_agg, 256>>>(b1, xwh_p, h1h_p, nrows);
    gcn_gemm_f16<<<nb_gemm, 256, GEMM2_SMEM_BYTES>>>(h1h_p, W2, xwh2_p, nrows);
    aggregate_kernel<<<nb_agg, 256>>>(b2, xwh2_p, out, nrows);
}